// round 8
// baseline (speedup 1.0000x reference)
#include <cuda_runtime.h>
#include <cuda_bf16.h>
#include <math.h>

// Problem constants (fixed by the dataset)
#define MAX_VISITS   510
#define B_CAP        128
#define TOTAL_VISITS_CAP 38400
#define D_DIM        256
#define D_VEC        (D_DIM / 4)   // 64 float4 per row
#define MAX_DAYS_M1  364.0f
#define N_ROWS_CAP   (B_CAP * MAX_VISITS)

// Scratch (allocation-free rule: __device__ globals).
// Zero-initialized at module load. slot_map encodes v+1; 0 = pad row.
// Pad entries are never written (constant 0); visit entries are rewritten
// with identical values every call, so work/output are call-invariant.
__device__ int g_slot_map[N_ROWS_CAP];
__device__ int g_seg_start[TOTAL_VISITS_CAP];
__device__ int g_seg_end[TOTAL_VISITS_CAP];
// Per-output-row packed code table: 16 ints (64B, int4-aligned), -1 = absent.
// Only rows with a visit are ever read (main checks slot_map first).
__device__ __align__(16) int g_packed[N_ROWS_CAP * 16];

// One thread handles 4 consecutive code_to_visit entries (int4) and detects
// segment boundaries; every visit has >=1 code so both bounds are always
// fully rewritten each call. Also scatters the visit->row map.
__global__ void vt_build_kernel(const int* __restrict__ code_to_visit,
                                const int* __restrict__ visit_person,
                                const int* __restrict__ visit_slot,
                                int total_codes, int total_visits) {
    int i = blockIdx.x * blockDim.x + threadIdx.x;
    int base = i * 4;
    if (base + 4 <= total_codes) {
        int4 c = *reinterpret_cast<const int4*>(code_to_visit + base);
        if (base == 0) g_seg_start[c.x] = 0;
        if (c.x != c.y) { g_seg_end[c.x] = base + 1; g_seg_start[c.y] = base + 1; }
        if (c.y != c.z) { g_seg_end[c.y] = base + 2; g_seg_start[c.z] = base + 2; }
        if (c.z != c.w) { g_seg_end[c.z] = base + 3; g_seg_start[c.w] = base + 3; }
        if (base + 4 == total_codes) {
            g_seg_end[c.w] = total_codes;
        } else {
            int nxt = code_to_visit[base + 4];
            if (c.w != nxt) { g_seg_end[c.w] = base + 4; g_seg_start[nxt] = base + 4; }
        }
    } else if (base < total_codes) {
        for (int k = base; k < total_codes; ++k) {
            int v = code_to_visit[k];
            if (k == 0 || code_to_visit[k - 1] != v) g_seg_start[v] = k;
            if (k == total_codes - 1 || code_to_visit[k + 1] != v) g_seg_end[v] = k + 1;
        }
    }
    if (i < total_visits) {
        g_slot_map[visit_person[i] * MAX_VISITS + visit_slot[i]] = i + 1;
    }
}

// One thread per visit: gather its <=16 codes into a 64B-aligned packed row
// (-1 sentinel) at the visit's output-row index. Runs after vt_build_kernel
// (same stream -> ordered).
__global__ void vt_pack_kernel(const int* __restrict__ all_codes,
                               const int* __restrict__ visit_person,
                               const int* __restrict__ visit_slot,
                               int total_visits) {
    int v = blockIdx.x * blockDim.x + threadIdx.x;
    if (v >= total_visits) return;
    int start = g_seg_start[v];
    int end   = g_seg_end[v];
    int row   = visit_person[v] * MAX_VISITS + visit_slot[v];

    int q[16];
    #pragma unroll
    for (int j = 0; j < 16; ++j)
        q[j] = (start + j < end) ? __ldg(all_codes + start + j) : -1;

    int4* dst = reinterpret_cast<int4*>(g_packed) + (size_t)row * 4;
    dst[0] = make_int4(q[0],  q[1],  q[2],  q[3]);
    dst[1] = make_int4(q[4],  q[5],  q[6],  q[7]);
    dst[2] = make_int4(q[8],  q[9],  q[10], q[11]);
    dst[3] = make_int4(q[12], q[13], q[14], q[15]);
}

// R7-winning body with the index path replaced by 4 aligned uniform int4
// loads from the packed table: 4 independent index loads each feeding 4
// independent predicated gathers (no barrier/shuffle/serialization in front
// of the gathers). 128-thread block handles 2 rows; 64 threads per row, one
// float4 each.
//
// CRITICAL: __launch_bounds__(128, 16) pins regs <= 32 so the full 64-warp
// occupancy is reachable (every regression this session traced to crossing
// that cliff).
__global__ __launch_bounds__(128, 16) void vt_main_kernel(
    const float* __restrict__ times,
    const float* __restrict__ concept_emb,
    const float* __restrict__ pad_embedding,
    const float* __restrict__ timescales,
    float* __restrict__ out,
    int n_rows) {
    int tid = threadIdx.x;                       // 0..127
    int row = blockIdx.x * 2 + (tid >> 6);       // 2 rows per block
    int t   = tid & 63;                          // lane within row: 0..63
    if (row >= n_rows) return;

    float4* out4 = reinterpret_cast<float4*>(out);

    int ve = g_slot_map[row];
    if (ve == 0) {
        // pad row
        float4 p = __ldg(reinterpret_cast<const float4*>(pad_embedding) + t);
        out4[(size_t)row * D_VEC + t] = p;
        return;
    }
    int v = ve - 1;

    const int4* pk = reinterpret_cast<const int4*>(g_packed) + (size_t)row * 4;
    int4 i0 = pk[0];
    int4 i1 = pk[1];
    int4 i2 = pk[2];
    int4 i3 = pk[3];

    const float4* emb4 = reinterpret_cast<const float4*>(concept_emb);
    float4 acc = make_float4(0.f, 0.f, 0.f, 0.f);

    int idx[16] = { i0.x, i0.y, i0.z, i0.w, i1.x, i1.y, i1.z, i1.w,
                    i2.x, i2.y, i2.z, i2.w, i3.x, i3.y, i3.z, i3.w };
    #pragma unroll
    for (int j = 0; j < 16; ++j) {
        int c = idx[j];
        if (c >= 0) {
            float4 r = __ldg(emb4 + (size_t)c * D_VEC + t);
            acc.x += r.x; acc.y += r.y; acc.z += r.z; acc.w += r.w;
        }
    }

    // Sinusoidal time embedding: out[d] += sin(t*ts[d]) (d<128) / cos(t*ts[d-128]).
    float tm = __ldg(times + v);
    tm = fminf(fmaxf(tm, 0.0f), MAX_DAYS_M1);

    int d0 = t * 4;
    float4 te;
    if (d0 < D_DIM / 2) {
        float a0 = tm * __ldg(timescales + d0 + 0);
        float a1 = tm * __ldg(timescales + d0 + 1);
        float a2 = tm * __ldg(timescales + d0 + 2);
        float a3 = tm * __ldg(timescales + d0 + 3);
        te.x = __sinf(a0); te.y = __sinf(a1); te.z = __sinf(a2); te.w = __sinf(a3);
    } else {
        int dh = d0 - D_DIM / 2;
        float a0 = tm * __ldg(timescales + dh + 0);
        float a1 = tm * __ldg(timescales + dh + 1);
        float a2 = tm * __ldg(timescales + dh + 2);
        float a3 = tm * __ldg(timescales + dh + 3);
        te.x = __cosf(a0); te.y = __cosf(a1); te.z = __cosf(a2); te.w = __cosf(a3);
    }

    acc.x += te.x; acc.y += te.y; acc.z += te.z; acc.w += te.w;
    out4[(size_t)row * D_VEC + t] = acc;
}

extern "C" void kernel_launch(void* const* d_in, const int* in_sizes, int n_in,
                              void* d_out, int out_size) {
    const int*   all_codes     = (const int*)d_in[0];
    const int*   code_to_visit = (const int*)d_in[1];
    const int*   visit_person  = (const int*)d_in[2];
    const int*   visit_slot    = (const int*)d_in[3];
    const float* times         = (const float*)d_in[4];
    const float* concept_emb   = (const float*)d_in[5];
    const float* pad_embedding = (const float*)d_in[6];
    const float* timescales    = (const float*)d_in[7];
    float* out = (float*)d_out;

    int total_codes  = in_sizes[0];
    int total_visits = in_sizes[2];
    int n_rows = out_size / D_DIM;   // B * MAX_VISITS

    int build_items = (total_codes + 3) / 4;
    if (build_items < total_visits) build_items = total_visits;
    vt_build_kernel<<<(build_items + 255) / 256, 256>>>(
        code_to_visit, visit_person, visit_slot, total_codes, total_visits);

    vt_pack_kernel<<<(total_visits + 255) / 256, 256>>>(
        all_codes, visit_person, visit_slot, total_visits);

    vt_main_kernel<<<(n_rows + 1) / 2, 128>>>(
        times, concept_emb, pad_embedding, timescales, out, n_rows);
}

// round 9
// speedup vs baseline: 1.0698x; 1.0698x over previous
#include <cuda_runtime.h>
#include <cuda_bf16.h>

// Problem constants (fixed by the dataset)
#define MAX_VISITS   510
#define B_CAP        128
#define TOTAL_VISITS_CAP 38400
#define D_DIM        256
#define D_VEC        (D_DIM / 4)   // 64 float4 per row
#define MAX_DAYS_M1  364.0f

// Scratch (allocation-free rule: __device__ globals).
// Zero-initialized at module load. slot_map encodes v+1; 0 = pad row.
// Pad entries are never written (constant 0); visit entries are rewritten
// with identical values every call, so work/output are call-invariant.
__device__ int g_slot_map[B_CAP * MAX_VISITS];
__device__ int g_seg_start[TOTAL_VISITS_CAP];
__device__ int g_seg_end[TOTAL_VISITS_CAP];

// One thread handles 4 consecutive code_to_visit entries (int4) and detects
// segment boundaries; every visit has >=1 code so both bounds are always
// fully rewritten each call. Also scatters the visit->row map.
__global__ void vt_build_kernel(const int* __restrict__ code_to_visit,
                                const int* __restrict__ visit_person,
                                const int* __restrict__ visit_slot,
                                int total_codes, int total_visits) {
    int i = blockIdx.x * blockDim.x + threadIdx.x;
    int base = i * 4;
    if (base + 4 <= total_codes) {
        int4 c = *reinterpret_cast<const int4*>(code_to_visit + base);
        if (base == 0) g_seg_start[c.x] = 0;
        if (c.x != c.y) { g_seg_end[c.x] = base + 1; g_seg_start[c.y] = base + 1; }
        if (c.y != c.z) { g_seg_end[c.y] = base + 2; g_seg_start[c.z] = base + 2; }
        if (c.z != c.w) { g_seg_end[c.z] = base + 3; g_seg_start[c.w] = base + 3; }
        if (base + 4 == total_codes) {
            g_seg_end[c.w] = total_codes;
        } else {
            int nxt = code_to_visit[base + 4];
            if (c.w != nxt) { g_seg_end[c.w] = base + 4; g_seg_start[nxt] = base + 4; }
        }
    } else if (base < total_codes) {
        for (int k = base; k < total_codes; ++k) {
            int v = code_to_visit[k];
            if (k == 0 || code_to_visit[k - 1] != v) g_seg_start[v] = k;
            if (k == total_codes - 1 || code_to_visit[k + 1] != v) g_seg_end[v] = k + 1;
        }
    }
    if (i < total_visits) {
        g_slot_map[visit_person[i] * MAX_VISITS + visit_slot[i]] = i + 1;
    }
}

// R7-winning structure, unchanged in front of the gathers: 128-thread block
// handles 2 rows; 64 threads per row, one float4 (4 consecutive dims) each.
// Per-thread predicated unroll-16 gather keeps 16 independent LDG.128 in
// flight (MLP=16); index loads are transient (LDG -> address -> gather),
// never all live at once.
//
// CRITICAL: __launch_bounds__(128, 16) pins regs <= 32 so the full 64-warp
// occupancy is reachable (every regression this session traced to crossing
// that cliff: 34+ regs -> 48-warp ceiling -> occ 65% -> +4us).
//
// Tail (only change vs R7): one float4 timescale load at (t & 31) — sin and
// cos halves use identical timescales — replacing 4 stride-16B scalar loads
// (16 wavefronts -> 4 per warp). __sinf/__cosf (RRO+MUFU); args <= 364 rad
// -> error ~2e-5 << 1e-3 tolerance.
__global__ __launch_bounds__(128, 16) void vt_main_kernel(
    const int* __restrict__ all_codes,
    const float* __restrict__ times,
    const float* __restrict__ concept_emb,
    const float* __restrict__ pad_embedding,
    const float* __restrict__ timescales,
    float* __restrict__ out,
    int n_rows) {
    int tid = threadIdx.x;                       // 0..127
    int row = blockIdx.x * 2 + (tid >> 6);       // 2 rows per block
    int t   = tid & 63;                          // lane within row: 0..63
    if (row >= n_rows) return;

    float4* out4 = reinterpret_cast<float4*>(out);

    int ve = g_slot_map[row];
    if (ve == 0) {
        // pad row
        float4 p = __ldg(reinterpret_cast<const float4*>(pad_embedding) + t);
        out4[(size_t)row * D_VEC + t] = p;
        return;
    }
    int v = ve - 1;

    int start = g_seg_start[v];
    int end   = g_seg_end[v];

    const float4* emb4 = reinterpret_cast<const float4*>(concept_emb);
    float4 acc = make_float4(0.f, 0.f, 0.f, 0.f);

    // <=16 codes per visit; fully unrolled predicated loop keeps all index
    // loads and data loads independent -> deep MLP into L2.
    #pragma unroll
    for (int j = 0; j < 16; ++j) {
        if (start + j < end) {
            int c = __ldg(all_codes + start + j);
            float4 r = __ldg(emb4 + (size_t)c * D_VEC + t);
            acc.x += r.x; acc.y += r.y; acc.z += r.z; acc.w += r.w;
        }
    }

    // Sinusoidal time embedding: out[d] += sin(t*ts[d]) (d<128) / cos(t*ts[d-128]).
    float tm = __ldg(times + v);
    tm = fminf(fmaxf(tm, 0.0f), MAX_DAYS_M1);
    float4 ts = __ldg(reinterpret_cast<const float4*>(timescales) + (t & 31));

    float4 te;
    if (t < 32) {
        te.x = __sinf(tm * ts.x); te.y = __sinf(tm * ts.y);
        te.z = __sinf(tm * ts.z); te.w = __sinf(tm * ts.w);
    } else {
        te.x = __cosf(tm * ts.x); te.y = __cosf(tm * ts.y);
        te.z = __cosf(tm * ts.z); te.w = __cosf(tm * ts.w);
    }

    acc.x += te.x; acc.y += te.y; acc.z += te.z; acc.w += te.w;
    out4[(size_t)row * D_VEC + t] = acc;
}

extern "C" void kernel_launch(void* const* d_in, const int* in_sizes, int n_in,
                              void* d_out, int out_size) {
    const int*   all_codes     = (const int*)d_in[0];
    const int*   code_to_visit = (const int*)d_in[1];
    const int*   visit_person  = (const int*)d_in[2];
    const int*   visit_slot    = (const int*)d_in[3];
    const float* times         = (const float*)d_in[4];
    const float* concept_emb   = (const float*)d_in[5];
    const float* pad_embedding = (const float*)d_in[6];
    const float* timescales    = (const float*)d_in[7];
    float* out = (float*)d_out;

    int total_codes  = in_sizes[0];
    int total_visits = in_sizes[2];
    int n_rows = out_size / D_DIM;   // B * MAX_VISITS

    int build_items = (total_codes + 3) / 4;
    if (build_items < total_visits) build_items = total_visits;
    vt_build_kernel<<<(build_items + 255) / 256, 256>>>(
        code_to_visit, visit_person, visit_slot, total_codes, total_visits);

    vt_main_kernel<<<(n_rows + 1) / 2, 128>>>(
        all_codes, times, concept_emb, pad_embedding, timescales, out, n_rows);
}